// round 1
// baseline (speedup 1.0000x reference)
#include <cuda_runtime.h>
#include <cstddef>

// ---------------------------------------------------------------------------
// gConv3d factorized:
//   q[n,o,b,h,w]   = sum_{c,fi,fj,fk} weight[o,c,fi,fj,fk,b] * x[c, xi+fi, yi+fj, zi+fk, h, w]
//   acc[n,g,o,h,w] = sum_{b,u,v} basis[g,b,u,v] * q[n,o,b,h+u,w+v]     (valid 6x38)
//   out[g*8+o, 1+xi,1+yi,1+zi, h, w] = acc[n, T[g,h,w], o, I[h,w]-1, J[h,w]-1]
//                                      + biassum[bias_basis[T[g,h,w]*8+o]]
//   everything else in out = 0
// Shapes: B=1, C=8, O=8, G=12, X=Y=Z=12, Xo=9, H=8, W=40, NB=7 basis fns.
// ---------------------------------------------------------------------------

#define N_SPATIAL 729          // 9^3 interior positions
#define Q_PER_N   17920        // 56 * 320
__device__ float g_q[N_SPATIAL * Q_PER_N];   // 52.25 MB scratch

// ---------------- Stage 1: q = weight (x) x  --------------------------------
// grid: 729 blocks (one per interior (xi,yi,zi)); 320 threads (one per (h,w)).
__global__ __launch_bounds__(320) void k_stage1(const float* __restrict__ x,
                                                const float* __restrict__ w) {
    __shared__ float sw[12096];                 // weight (8,8,27,7)
    const int n = blockIdx.x;
    const int zi = n % 9, yi = (n / 9) % 9, xi = n / 81;
    const int t = threadIdx.x;                  // hw index 0..319

    for (int i = t; i < 12096; i += 320) sw[i] = w[i];
    __syncthreads();

    float acc[56];
#pragma unroll
    for (int i = 0; i < 56; i++) acc[i] = 0.f;

    for (int c = 0; c < 8; c++) {
        const float* xp = x + ((size_t)(((c * 12 + xi) * 12 + yi) * 12 + zi)) * 320 + t;
        const float* wp = sw + c * 189;         // c*27*7
#pragma unroll 1
        for (int f = 0; f < 27; f++) {
            const int fi = f / 9, r = f - fi * 9;
            const int fj = r / 3, fk = r - fj * 3;
            const float xv = __ldg(xp + (fi * 144 + fj * 12 + fk) * 320);
            const float* wq = wp + f * 7;
#pragma unroll
            for (int o = 0; o < 8; o++)
#pragma unroll
                for (int b = 0; b < 7; b++)
                    acc[o * 7 + b] = fmaf(wq[o * 1512 + b], xv, acc[o * 7 + b]);
        }
    }

    float* qp = g_q + (size_t)n * Q_PER_N + t;
#pragma unroll
    for (int i = 0; i < 56; i++) qp[i * 320] = acc[i];
}

// ---------------- Stage 2: basis conv + gather/scatter ----------------------
// grid: 1728 blocks (one per (x,y,z) in 12^3); 512 threads.
// Dynamic SMEM layout (floats):
//   sq    [56][8][41]  = 18368   (q tile, pitch-padded)
//   sacc  [576][39]    = 22464   (acc tile (g,o,hc) x wc, pitch-padded)
//   sbasis             = 756
//   sbiasv             = 96
//   sT(int)            = 3840
//   sI(int), sJ(int)   = 320+320
#define S2_SMEM_FLOATS (18368 + 22464 + 756 + 96 + 3840 + 320 + 320)
#define S2_SMEM_BYTES  (S2_SMEM_FLOATS * 4)

__global__ __launch_bounds__(512) void k_stage2(const float* __restrict__ bias,
                                                const float* __restrict__ basis,
                                                const int* __restrict__ Ig,
                                                const int* __restrict__ Jg,
                                                const int* __restrict__ Tg,
                                                const int* __restrict__ bbg,
                                                float* __restrict__ out) {
    extern __shared__ float smem[];
    float* sq     = smem;                   // 18368
    float* sacc   = sq + 18368;             // 22464
    float* sbasis = sacc + 22464;           // 756
    float* sbiasv = sbasis + 756;           // 96
    int*   sT     = (int*)(sbiasv + 96);    // 3840
    int*   sI     = sT + 3840;              // 320
    int*   sJ     = sI + 320;               // 320

    const int bx = blockIdx.x;
    const int z = bx % 12, y = (bx / 12) % 12, xx = bx / 144;
    const int tid = threadIdx.x;

    const bool border = (xx < 1) | (xx > 9) | (y < 1) | (y > 9) | (z < 1) | (z > 9);
    if (border) {
        const float4 zv = make_float4(0.f, 0.f, 0.f, 0.f);
        float4* ob = (float4*)out;
        for (int e = tid; e < 96 * 80; e += 512) {
            const int go = e / 80, k = e - go * 80;
            ob[((size_t)go * 1728 + bx) * 80 + k] = zv;
        }
        return;
    }

    const int n = (xx - 1) * 81 + (y - 1) * 9 + (z - 1);

    // ---- Phase A: stage SMEM ----
    const float4* qg = (const float4*)(g_q + (size_t)n * Q_PER_N);
    for (int i4 = tid; i4 < 4480; i4 += 512) {
        const float4 v = qg[i4];
        const int row = i4 / 10, k = (i4 - row * 10) * 4;
        float* d = sq + row * 41 + k;
        d[0] = v.x; d[1] = v.y; d[2] = v.z; d[3] = v.w;
    }
    for (int i = tid; i < 756; i += 512) sbasis[i] = basis[i];
    for (int i = tid; i < 3840; i += 512) sT[i] = Tg[i];
    if (tid < 320) { sI[tid] = Ig[tid]; sJ[tid] = Jg[tid]; }
    if (tid < 96) {
        const int b = bbg[tid];
        float s = 0.f;
        for (int k = 0; k < 27; k++) s += bias[b * 27 + k];
        sbiasv[tid] = s;
    }
    __syncthreads();

    // ---- Phase B: acc[g,o,hc,wc] = sum_{b,u,v} basis * q (valid conv) ----
    // 1152 tasks = 576 rows (g,o,hc) x 2 half-width chunks (19 each).
    for (int task = tid; task < 1152; task += 512) {
        const int chunk = task & 1, row = task >> 1;
        const int hc = row % 6, od = row / 6;
        const int o = od & 7, g = od >> 3;
        const int wc0 = chunk * 19;

        float accv[19];
#pragma unroll
        for (int i = 0; i < 19; i++) accv[i] = 0.f;

        const float* bgp = sbasis + g * 63;
#pragma unroll 1
        for (int b = 0; b < 7; b++) {
            const float* qrow = sq + (o * 7 + b) * 8 * 41 + wc0;
#pragma unroll
            for (int u = 0; u < 3; u++) {
                const float* qr = qrow + (hc + u) * 41;
                const float b0 = bgp[b * 9 + u * 3 + 0];
                const float b1 = bgp[b * 9 + u * 3 + 1];
                const float b2 = bgp[b * 9 + u * 3 + 2];
                float qv[21];
#pragma unroll
                for (int k = 0; k < 21; k++) qv[k] = qr[k];
#pragma unroll
                for (int i = 0; i < 19; i++)
                    accv[i] = fmaf(b0, qv[i],
                              fmaf(b1, qv[i + 1],
                              fmaf(b2, qv[i + 2], accv[i])));
            }
        }
        float* ap = sacc + row * 39 + wc0;
#pragma unroll
        for (int i = 0; i < 19; i++) ap[i] = accv[i];
    }
    __syncthreads();

    // ---- Phase C: gather via T/I/J, add bias, scatter to out ----
    for (int e = tid; e < 30720; e += 512) {
        const int go = e / 320, hw = e - go * 320;
        const int g = go >> 3, o = go & 7;
        const int gg = sT[g * 320 + hw];
        const int ii = sI[hw] - 1, jj = sJ[hw] - 1;
        const float v = sacc[((gg * 8 + o) * 6 + ii) * 39 + jj] + sbiasv[gg * 8 + o];
        out[((size_t)go * 1728 + bx) * 320 + hw] = v;
    }
}

// ---------------------------------------------------------------------------
extern "C" void kernel_launch(void* const* d_in, const int* in_sizes, int n_in,
                              void* d_out, int out_size) {
    const float* x     = (const float*)d_in[0];
    const float* wgt   = (const float*)d_in[1];
    const float* bias  = (const float*)d_in[2];
    const float* basis = (const float*)d_in[3];
    const int*   Ig    = (const int*)d_in[4];
    const int*   Jg    = (const int*)d_in[5];
    const int*   Tg    = (const int*)d_in[6];
    const int*   bbg   = (const int*)d_in[7];
    float* out = (float*)d_out;

    // Attribute set is idempotent and not a stream op (capture-safe).
    cudaFuncSetAttribute(k_stage2, cudaFuncAttributeMaxDynamicSharedMemorySize,
                         S2_SMEM_BYTES);

    k_stage1<<<N_SPATIAL, 320>>>(x, wgt);
    k_stage2<<<1728, 512, S2_SMEM_BYTES>>>(bias, basis, Ig, Jg, Tg, bbg, out);
}

// round 2
// speedup vs baseline: 2.0217x; 2.0217x over previous
#include <cuda_runtime.h>
#include <cstddef>

// ---------------------------------------------------------------------------
// Fused gConv3d:
//   q[ob,h,w]      = sum_{c,f} wT[c,f,ob] * x[c, xi+fi, yi+fj, zi+fk, h, w]   (SMEM)
//   acc[g,o,hc,wc] = sum_{b,u,v} basis[g,b,u,v] * q[o*7+b, hc+u, wc+v]        (SMEM)
//   out[go, x,y,z, h, w] = acc[T[g,h,w], o, I[h,w]-1, J[h,w]-1] + biassum[...]
//   border spatial blocks -> zeros.
// Shapes: C=8, O=8, G=12, X=12, interior 9^3=729, H=8, W=40, NB=7.
// One block per (x,y,z) in 12^3 = 1728 blocks, 640 threads.
// ---------------------------------------------------------------------------

// SMEM layout (floats):
//   sq    [56][8][41] = 18368        (q tile)
//   union { sw[12096] (weights, stage1) ; sacc[576][39] = 22464 (phase B/C) }
//   sbasis 756, sbiasv 96, sT 3840(int), sI 320(int), sJ 320(int)
#define SQ_OFF     0
#define SW_OFF     18368
#define SACC_OFF   18368
#define SBASIS_OFF 40832
#define SBIAS_OFF  41588
#define ST_OFF     41684
#define SI_OFF     45524
#define SJ_OFF     45844
#define SMEM_FLOATS 46164
#define SMEM_BYTES  (SMEM_FLOATS * 4)

__global__ __launch_bounds__(640) void k_fused(const float* __restrict__ x,
                                               const float* __restrict__ wgt,
                                               const float* __restrict__ bias,
                                               const float* __restrict__ basis,
                                               const int* __restrict__ Ig,
                                               const int* __restrict__ Jg,
                                               const int* __restrict__ Tg,
                                               const int* __restrict__ bbg,
                                               float* __restrict__ out) {
    extern __shared__ float smem[];
    float* sq     = smem + SQ_OFF;
    float* sw     = smem + SW_OFF;
    float* sacc   = smem + SACC_OFF;
    float* sbasis = smem + SBASIS_OFF;
    float* sbiasv = smem + SBIAS_OFF;
    int*   sT     = (int*)(smem + ST_OFF);
    int*   sI     = (int*)(smem + SI_OFF);
    int*   sJ     = (int*)(smem + SJ_OFF);

    const int bx  = blockIdx.x;
    const int z   = bx % 12, y = (bx / 12) % 12, xx = bx / 144;
    const int tid = threadIdx.x;

    const bool border = (xx < 1) | (xx > 9) | (y < 1) | (y > 9) | (z < 1) | (z > 9);
    if (border) {
        const float4 zv = make_float4(0.f, 0.f, 0.f, 0.f);
        float4* ob4 = (float4*)out;
        // out as float4: [96][1728][80]
        for (int e = tid; e < 96 * 80; e += 640) {
            const int go = e / 80, k = e - go * 80;
            ob4[(size_t)go * 138240 + (size_t)bx * 80 + k] = zv;
        }
        return;
    }

    // ---- Phase 0: stage weights (transposed -> sw[(c*27+f)*56 + o*7+b]) & misc
    for (int idx = tid; idx < 12096; idx += 640) {
        const int ob = idx % 56;
        const int cf = idx / 56;
        const int f  = cf % 27;
        const int c  = cf / 27;
        const int o  = ob / 7, b = ob % 7;
        sw[idx] = wgt[((o * 8 + c) * 27 + f) * 7 + b];
    }
    for (int i = tid; i < 756; i += 640) sbasis[i] = basis[i];
    for (int i = tid; i < 3840; i += 640) sT[i] = Tg[i];
    if (tid < 320) { sI[tid] = Ig[tid]; sJ[tid] = Jg[tid]; }
    if (tid >= 512 && tid < 608) {
        const int t2 = tid - 512;
        const int b  = bbg[t2];
        float s = 0.f;
        for (int k = 0; k < 27; k++) s += bias[b * 27 + k];
        sbiasv[t2] = s;
    }
    __syncthreads();

    // ---- Stage 1: q = weight (x) x, 2 hw x 14 ob per thread -----------------
    const int xi = xx - 1, yi = y - 1, zi = z - 1;
    const int hw0 = (tid % 160) * 2;            // even hw pair
    const int obg = tid / 160;                  // warp-uniform (warps 0-4 -> 0, ...)
    const int ob0 = obg * 14;

    float acc[28];
#pragma unroll
    for (int i = 0; i < 28; i++) acc[i] = 0.f;

#pragma unroll 1
    for (int c = 0; c < 8; c++) {
        const float* xpc = x + (size_t)(((c * 12 + xi) * 12 + yi) * 12 + zi) * 320 + hw0;
        const float* wp  = sw + c * 1512 + ob0;  // c*27*56
#pragma unroll
        for (int fi = 0; fi < 3; fi++) {
#pragma unroll
            for (int fj = 0; fj < 3; fj++) {
                const float* xq = xpc + (fi * 144 + fj * 12) * 320;
                const float* wq = wp + (fi * 3 + fj) * 168;   // *3*56
#pragma unroll
                for (int fk = 0; fk < 3; fk++) {
                    const float2 xv = *(const float2*)(xq + fk * 320);
                    const float* wr = wq + fk * 56;
#pragma unroll
                    for (int j = 0; j < 14; j++) {
                        const float wv = wr[j];
                        acc[j * 2]     = fmaf(wv, xv.x, acc[j * 2]);
                        acc[j * 2 + 1] = fmaf(wv, xv.y, acc[j * 2 + 1]);
                    }
                }
            }
        }
    }

    // store q tile: sq[ob][h][41] with hw = h*40+w
    {
        const int h = hw0 / 40, w = hw0 - h * 40;   // w even, w+1 <= 39
        float* qb = sq + h * 41 + w;
#pragma unroll
        for (int j = 0; j < 14; j++) {
            qb[(ob0 + j) * 328]     = acc[j * 2];
            qb[(ob0 + j) * 328 + 1] = acc[j * 2 + 1];
        }
    }
    __syncthreads();   // sw dead from here; sacc (aliased) becomes live

    // ---- Phase B: acc[g,o,hc,wc] = sum_{b,u,v} basis * q (valid 6x38) -------
    for (int task = tid; task < 1152; task += 640) {
        const int chunk = task & 1, row = task >> 1;
        const int hc = row % 6, od = row / 6;
        const int o = od & 7, g = od >> 3;
        const int wc0 = chunk * 19;

        float accv[19];
#pragma unroll
        for (int i = 0; i < 19; i++) accv[i] = 0.f;

        const float* bgp = sbasis + g * 63;
#pragma unroll 1
        for (int b = 0; b < 7; b++) {
            const float* qrow = sq + (o * 7 + b) * 328 + wc0;
#pragma unroll
            for (int u = 0; u < 3; u++) {
                const float* qr = qrow + (hc + u) * 41;
                const float b0 = bgp[b * 9 + u * 3 + 0];
                const float b1 = bgp[b * 9 + u * 3 + 1];
                const float b2 = bgp[b * 9 + u * 3 + 2];
                float qv[21];
#pragma unroll
                for (int k = 0; k < 21; k++) qv[k] = qr[k];
#pragma unroll
                for (int i = 0; i < 19; i++)
                    accv[i] = fmaf(b0, qv[i],
                              fmaf(b1, qv[i + 1],
                              fmaf(b2, qv[i + 2], accv[i])));
            }
        }
        float* ap = sacc + row * 39 + wc0;
#pragma unroll
        for (int i = 0; i < 19; i++) ap[i] = accv[i];
    }
    __syncthreads();

    // ---- Phase C: gather via T/I/J, add bias, write out ---------------------
    {
        const int hw   = tid % 320;
        const int half = tid / 320;
        const int ii = sI[hw] - 1, jj = sJ[hw] - 1;
        const int pix = ii * 39 + jj;
        const size_t obase = (size_t)bx * 320 + hw;
        const int* tp = sT + hw;
#pragma unroll 1
        for (int go = half; go < 96; go += 2) {
            const int g = go >> 3, o = go & 7;
            const int gg = tp[g * 320];
            const int idx = gg * 8 + o;
            const float v = sacc[idx * 234 + pix] + sbiasv[idx];   // 6*39=234
            out[(size_t)go * 552960 + obase] = v;                   // 1728*320
        }
    }
}

// ---------------------------------------------------------------------------
extern "C" void kernel_launch(void* const* d_in, const int* in_sizes, int n_in,
                              void* d_out, int out_size) {
    const float* x     = (const float*)d_in[0];
    const float* wgt   = (const float*)d_in[1];
    const float* bias  = (const float*)d_in[2];
    const float* basis = (const float*)d_in[3];
    const int*   Ig    = (const int*)d_in[4];
    const int*   Jg    = (const int*)d_in[5];
    const int*   Tg    = (const int*)d_in[6];
    const int*   bbg   = (const int*)d_in[7];
    float* out = (float*)d_out;

    cudaFuncSetAttribute(k_fused, cudaFuncAttributeMaxDynamicSharedMemorySize,
                         SMEM_BYTES);

    k_fused<<<1728, 640, SMEM_BYTES>>>(x, wgt, bias, basis, Ig, Jg, Tg, bbg, out);
}

// round 5
// speedup vs baseline: 2.3238x; 1.1494x over previous
#include <cuda_runtime.h>
#include <cstddef>

// ---------------------------------------------------------------------------
// Fused gConv3d, f32x2-packed:
//   q[ob,h,w]      = sum_{c,f} wT[c,f,ob] * x[c, xi+fi, yi+fj, zi+fk, h, w]
//   acc[g,o,hc,wc] = sum_{b,u,v} basis[g,b,u,v] * q[o*7+b, hc+u, wc+v]
//   out[go,x,y,z,h,w] = acc[T[g,h,w], o, I-1, J-1] + biassum ; border -> 0
// One block per (x,y,z) in 12^3 = 1728 blocks, 640 threads.
// ---------------------------------------------------------------------------

typedef unsigned long long u64;

__device__ __forceinline__ u64 ffma2(u64 a, u64 b, u64 c) {
    u64 d;
    asm("fma.rn.f32x2 %0,%1,%2,%3;" : "=l"(d) : "l"(a), "l"(b), "l"(c));
    return d;
}
__device__ __forceinline__ u64 pack2(float lo, float hi) {
    u64 d;
    asm("mov.b64 %0,{%1,%2};" : "=l"(d) : "f"(lo), "f"(hi));
    return d;
}
__device__ __forceinline__ void unpack2(u64 v, float& lo, float& hi) {
    asm("mov.b64 {%0,%1},%2;" : "=f"(lo), "=f"(hi) : "l"(v));
}

// SMEM layout (floats):
//   sq [56][8][42] = 18816 (pitch 42, row stride 336)
//   union @18816: sw[13824] (stage1 weights) | sacc[96][234]=22464 (B/C)
//   sbasis 756, sbiasv 96, sT 3840(int), sI 320(int), sJ 320(int)
#define SQ_OFF     0
#define SW_OFF     18816
#define SACC_OFF   18816
#define SBASIS_OFF 41280
#define SBIAS_OFF  42036
#define ST_OFF     42132
#define SI_OFF     45972
#define SJ_OFF     46292
#define SMEM_FLOATS 46612
#define SMEM_BYTES  (SMEM_FLOATS * 4)

__global__ __launch_bounds__(640) void k_fused(const float* __restrict__ x,
                                               const float* __restrict__ wgt,
                                               const float* __restrict__ bias,
                                               const float* __restrict__ basis,
                                               const int* __restrict__ Ig,
                                               const int* __restrict__ Jg,
                                               const int* __restrict__ Tg,
                                               const int* __restrict__ bbg,
                                               float* __restrict__ out) {
    extern __shared__ float smem[];
    float* sq     = smem + SQ_OFF;
    float* sw     = smem + SW_OFF;
    float* sacc   = smem + SACC_OFF;
    float* sbasis = smem + SBASIS_OFF;
    float* sbiasv = smem + SBIAS_OFF;
    int*   sT     = (int*)(smem + ST_OFF);
    int*   sI     = (int*)(smem + SI_OFF);
    int*   sJ     = (int*)(smem + SJ_OFF);

    const int bx  = blockIdx.x;
    const int z   = bx % 12, y = (bx / 12) % 12, xx = bx / 144;
    const int tid = threadIdx.x;

    const bool border = (xx < 1) | (xx > 9) | (y < 1) | (y > 9) | (z < 1) | (z > 9);
    if (border) {
        const float4 zv = make_float4(0.f, 0.f, 0.f, 0.f);
        float4* ob4 = (float4*)out;
        for (int e = tid; e < 96 * 80; e += 640) {
            const int go = e / 80, k = e - go * 80;
            ob4[(size_t)go * 138240 + (size_t)bx * 80 + k] = zv;
        }
        return;
    }

    // ---- Phase 0: stage weights into padded-transposed layout ----
    // sw[(c*27+f)*64 + obg*16 + j] = wgt[((o*8+c)*27+f)*7 + b], ob = obg*14+j
    for (int idx = tid; idx < 13824; idx += 640) {
        const int cf  = idx >> 6;
        const int rem = idx & 63;
        const int obg = rem >> 4, j = rem & 15;
        float v = 0.f;
        if (j < 14) {
            const int ob = obg * 14 + j;
            const int o = ob / 7, b = ob - o * 7;
            const int c = cf / 27, f = cf - c * 27;
            v = wgt[((o * 8 + c) * 27 + f) * 7 + b];
        }
        sw[idx] = v;
    }
    for (int i = tid; i < 756; i += 640) sbasis[i] = basis[i];
    for (int i = tid; i < 3840; i += 640) sT[i] = Tg[i];
    if (tid < 320) { sI[tid] = Ig[tid]; sJ[tid] = Jg[tid]; }
    if (tid >= 512 && tid < 608) {
        const int t2 = tid - 512;
        const int b  = bbg[t2];
        float s = 0.f;
        for (int k = 0; k < 27; k++) s += bias[b * 27 + k];
        sbiasv[t2] = s;
    }
    __syncthreads();

    // ---- Stage 1: 2 hw x 14 ob per thread, FFMA2 over ob-pairs -------------
    const int xi = xx - 1, yi = y - 1, zi = z - 1;
    const int hw0 = (tid % 160) * 2;
    const int obg = tid / 160;                 // 0..3 (warp-uniform)
    const int ob0 = obg * 14;

    u64 acc2[14];                              // [pair p][hw s] -> acc2[2p+s]
#pragma unroll
    for (int i = 0; i < 14; i++) acc2[i] = 0ull;

#pragma unroll 1
    for (int c = 0; c < 8; c++) {
        const float* xpc = x + (size_t)(((c * 12 + xi) * 12 + yi) * 12 + zi) * 320 + hw0;
        const float* wpc = sw + c * 1728 + obg * 16;
#pragma unroll
        for (int fi = 0; fi < 3; fi++) {
#pragma unroll
            for (int fj = 0; fj < 3; fj++) {
                const float* xq = xpc + (fi * 144 + fj * 12) * 320;
                const float* wq = wpc + (fi * 9 + fj * 3) * 64;
#pragma unroll
                for (int fk = 0; fk < 3; fk++) {
                    const float2 xv = *(const float2*)(xq + fk * 320);
                    const u64 x0 = pack2(xv.x, xv.x);
                    const u64 x1 = pack2(xv.y, xv.y);
                    const ulonglong2* wv = (const ulonglong2*)(wq + fk * 64);
                    const ulonglong2 wa = wv[0];
                    const ulonglong2 wb = wv[1];
                    const ulonglong2 wcp = wv[2];
                    const ulonglong2 wd = wv[3];
                    acc2[0]  = ffma2(wa.x, x0, acc2[0]);
                    acc2[1]  = ffma2(wa.x, x1, acc2[1]);
                    acc2[2]  = ffma2(wa.y, x0, acc2[2]);
                    acc2[3]  = ffma2(wa.y, x1, acc2[3]);
                    acc2[4]  = ffma2(wb.x, x0, acc2[4]);
                    acc2[5]  = ffma2(wb.x, x1, acc2[5]);
                    acc2[6]  = ffma2(wb.y, x0, acc2[6]);
                    acc2[7]  = ffma2(wb.y, x1, acc2[7]);
                    acc2[8]  = ffma2(wcp.x, x0, acc2[8]);
                    acc2[9]  = ffma2(wcp.x, x1, acc2[9]);
                    acc2[10] = ffma2(wcp.y, x0, acc2[10]);
                    acc2[11] = ffma2(wcp.y, x1, acc2[11]);
                    acc2[12] = ffma2(wd.x, x0, acc2[12]);
                    acc2[13] = ffma2(wd.x, x1, acc2[13]);
                }
            }
        }
    }

    // store q tile: sq[ob*336 + h*42 + w]
    {
        const int h = hw0 / 40, w = hw0 - h * 40;   // hw0 even, hw0+1 same h
        float* qb = sq + h * 42 + w;
#pragma unroll
        for (int p = 0; p < 7; p++) {
            float a0, a1, b0, b1;
            unpack2(acc2[2 * p], a0, a1);       // (ob0+2p, ob0+2p+1) at hw0
            unpack2(acc2[2 * p + 1], b0, b1);   // same obs at hw0+1
            float* r0 = qb + (ob0 + 2 * p) * 336;
            float* r1 = qb + (ob0 + 2 * p + 1) * 336;
            r0[0] = a0; r0[1] = b0;
            r1[0] = a1; r1[1] = b1;
        }
    }
    __syncthreads();   // sw dead; sacc live

    // ---- Phase B: FFMA2 over g-pairs -----------------------------------------
    // tasks: gpair(6) x o(8) x hc(6) x chunk(4); chunk widths 10/10/10/8.
    for (int task = tid; task < 1152; task += 640) {
        const int chunk = task & 3;
        int r = task >> 2;
        const int hc = r % 6; r /= 6;
        const int o = r & 7;
        const int gp = r >> 3;
        const int g0 = gp * 2;
        const int wc0 = chunk * 10;
        const int width = (chunk < 3) ? 10 : 8;

        u64 accv[10];
#pragma unroll
        for (int i = 0; i < 10; i++) accv[i] = 0ull;

#pragma unroll 1
        for (int b = 0; b < 7; b++) {
            const float* ba = sbasis + g0 * 63 + b * 9;
            const float* bb = ba + 63;
            u64 bp[9];
#pragma unroll
            for (int t = 0; t < 9; t++) bp[t] = pack2(ba[t], bb[t]);

            const float* qbase = sq + (o * 7 + b) * 336 + wc0;
#pragma unroll
            for (int u = 0; u < 3; u++) {
                const float* qr = qbase + (hc + u) * 42;
                u64 qp[12];
#pragma unroll
                for (int k = 0; k < 6; k++) {
                    const float2 qv = *(const float2*)(qr + 2 * k);
                    qp[2 * k]     = pack2(qv.x, qv.x);
                    qp[2 * k + 1] = pack2(qv.y, qv.y);
                }
                const u64 c0 = bp[u * 3 + 0], c1 = bp[u * 3 + 1], c2 = bp[u * 3 + 2];
#pragma unroll
                for (int i = 0; i < 10; i++)
                    accv[i] = ffma2(c0, qp[i],
                              ffma2(c1, qp[i + 1],
                              ffma2(c2, qp[i + 2], accv[i])));
            }
        }
        // sacc[(g*8+o)*234 + hc*39 + wc]
        float* a0p = sacc + (g0 * 8 + o) * 234 + hc * 39 + wc0;
        float* a1p = a0p + 8 * 234;
#pragma unroll
        for (int i = 0; i < 10; i++) {
            if (i < width) {
                float v0, v1;
                unpack2(accv[i], v0, v1);
                a0p[i] = v0;
                a1p[i] = v1;
            }
        }
    }
    __syncthreads();

    // ---- Phase C: gather via T/I/J, add bias, write out ---------------------
    {
        const int hw   = tid % 320;
        const int half = tid / 320;
        const int ii = sI[hw] - 1, jj = sJ[hw] - 1;
        const int pix = ii * 39 + jj;
        const size_t obase = (size_t)bx * 320 + hw;
        const int* tp = sT + hw;
#pragma unroll 1
        for (int go = half; go < 96; go += 2) {
            const int g = go >> 3, o = go & 7;
            const int gg = tp[g * 320];
            const int idx = gg * 8 + o;
            const float v = sacc[idx * 234 + pix] + sbiasv[idx];
            out[(size_t)go * 552960 + obase] = v;
        }
    }
}

// ---------------------------------------------------------------------------
extern "C" void kernel_launch(void* const* d_in, const int* in_sizes, int n_in,
                              void* d_out, int out_size) {
    const float* x     = (const float*)d_in[0];
    const float* wgt   = (const float*)d_in[1];
    const float* bias  = (const float*)d_in[2];
    const float* basis = (const float*)d_in[3];
    const int*   Ig    = (const int*)d_in[4];
    const int*   Jg    = (const int*)d_in[5];
    const int*   Tg    = (const int*)d_in[6];
    const int*   bbg   = (const int*)d_in[7];
    float* out = (float*)d_out;

    cudaFuncSetAttribute(k_fused, cudaFuncAttributeMaxDynamicSharedMemorySize,
                         SMEM_BYTES);

    k_fused<<<1728, 640, SMEM_BYTES>>>(x, wgt, bias, basis, Ig, Jg, Tg, bbg, out);
}

// round 10
// speedup vs baseline: 2.6939x; 1.1592x over previous
#include <cuda_runtime.h>
#include <cstddef>

// ---------------------------------------------------------------------------
// Fused gConv3d, f32x2-packed (no constant memory):
//   q[ob,h,w]      = sum_{c,f} wT[c,f,ob] * x[c, xi+fi, yi+fj, zi+fk, h, w]
//   acc[g,o,hc,wc] = sum_{b,u,v} basis[g,b,u,v] * q[o*7+b, hc+u, wc+v]
//   out[go,x,y,z,h,w] = acc[gg, o, ii, jj] + biassum ;  border blocks -> 0
//   gg/ii/jj computed analytically:
//     border(h,w) = h==0|h==7|w==0|w==39 ; gg = border ? (g+1)%12 : g
//     ii = clip(h,1,6)-1 ; jj = clip(w,1,38)-1
// 1728 blocks (one per (x,y,z)), 640 threads.
// ---------------------------------------------------------------------------

typedef unsigned long long u64;

__device__ __forceinline__ u64 ffma2(u64 a, u64 b, u64 c) {
    u64 d;
    asm("fma.rn.f32x2 %0,%1,%2,%3;" : "=l"(d) : "l"(a), "l"(b), "l"(c));
    return d;
}
__device__ __forceinline__ u64 pack2(float lo, float hi) {
    u64 d;
    asm("mov.b64 %0,{%1,%2};" : "=l"(d) : "f"(lo), "f"(hi));
    return d;
}
__device__ __forceinline__ void unpack2(u64 v, float& lo, float& hi) {
    asm("mov.b64 {%0,%1},%2;" : "=f"(lo), "=f"(hi) : "l"(v));
}

// SMEM layout (floats):
//   sq   [56][8][50] = 22400   (row pitch 50, ob stride 400)
//   union @22400: sw[13824] (stage-1 weights) | sacc[96][234] = 22464
//   sbp  756 (basis pre-paired (g0,g1) interleaved)
//   sbiasv 96
#define SQ_OFF     0
#define SW_OFF     22400
#define SACC_OFF   22400
#define SBP_OFF    44864
#define SBIAS_OFF  45620
#define SMEM_FLOATS 45716
#define SMEM_BYTES  (SMEM_FLOATS * 4)

__global__ __launch_bounds__(640) void k_fused(const float* __restrict__ x,
                                               const float* __restrict__ wgt,
                                               const float* __restrict__ bias,
                                               const float* __restrict__ basis,
                                               const int* __restrict__ bbg,
                                               float* __restrict__ out) {
    extern __shared__ float smem[];
    float* sq     = smem + SQ_OFF;
    float* sw     = smem + SW_OFF;
    float* sacc   = smem + SACC_OFF;
    float* sbp    = smem + SBP_OFF;
    float* sbiasv = smem + SBIAS_OFF;

    const int bx  = blockIdx.x;
    const int z   = bx % 12, y = (bx / 12) % 12, xx = bx / 144;
    const int tid = threadIdx.x;

    const bool borderblk = (xx < 1) | (xx > 9) | (y < 1) | (y > 9) | (z < 1) | (z > 9);
    if (borderblk) {
        const float4 zv = make_float4(0.f, 0.f, 0.f, 0.f);
        float4* ob4 = (float4*)out;
        for (int e = tid; e < 96 * 80; e += 640) {
            const int go = e / 80, k = e - go * 80;
            ob4[(size_t)go * 138240 + (size_t)bx * 80 + k] = zv;
        }
        return;
    }

    // ---- Phase 0: stage weights (transposed+padded), paired basis, biassums --
    // sw[(c*27+f)*64 + obg*16 + j] = wgt[((o*8+c)*27+f)*7+b], ob = obg*14+j
    for (int idx = tid; idx < 13824; idx += 640) {
        const int cf  = idx >> 6;
        const int rem = idx & 63;
        const int obg = rem >> 4, j = rem & 15;
        float v = 0.f;
        if (j < 14) {
            const int ob = obg * 14 + j;
            const int o = ob / 7, b = ob - o * 7;
            const int c = cf / 27, f = cf - c * 27;
            v = wgt[((o * 8 + c) * 27 + f) * 7 + b];
        }
        sw[idx] = v;
    }
    for (int i = tid; i < 378; i += 640) {
        const int gp = i / 63, r = i - gp * 63;
        sbp[2 * i]     = basis[gp * 126 + r];        // g = 2*gp
        sbp[2 * i + 1] = basis[gp * 126 + 63 + r];   // g = 2*gp+1
    }
    if (tid >= 512 && tid < 608) {
        const int t2 = tid - 512;
        const int b  = bbg[t2];
        float s = 0.f;
        for (int k = 0; k < 27; k++) s += bias[b * 27 + k];
        sbiasv[t2] = s;
    }
    __syncthreads();

    // ---- Stage 1: 2 hw x 14 ob per thread, FFMA2 over ob-pairs (as R5) ------
    const int xi = xx - 1, yi = y - 1, zi = z - 1;
    const int hw0 = (tid % 160) * 2;
    const int obg = tid / 160;                 // 0..3 (warp-uniform)
    const int ob0 = obg * 14;

    u64 acc2[14];
#pragma unroll
    for (int i = 0; i < 14; i++) acc2[i] = 0ull;

#pragma unroll 1
    for (int c = 0; c < 8; c++) {
        const float* xpc = x + (size_t)(((c * 12 + xi) * 12 + yi) * 12 + zi) * 320 + hw0;
        const float* wpc = sw + c * 1728 + obg * 16;
#pragma unroll
        for (int fi = 0; fi < 3; fi++) {
#pragma unroll
            for (int fj = 0; fj < 3; fj++) {
                const float* xq = xpc + (fi * 144 + fj * 12) * 320;
                const float* wq = wpc + (fi * 9 + fj * 3) * 64;
#pragma unroll
                for (int fk = 0; fk < 3; fk++) {
                    const float2 xv = *(const float2*)(xq + fk * 320);
                    const u64 x0 = pack2(xv.x, xv.x);
                    const u64 x1 = pack2(xv.y, xv.y);
                    const ulonglong2* wv = (const ulonglong2*)(wq + fk * 64);
                    const ulonglong2 wa  = wv[0];
                    const ulonglong2 wb  = wv[1];
                    const ulonglong2 wcp = wv[2];
                    const ulonglong2 wd  = wv[3];
                    acc2[0]  = ffma2(wa.x, x0, acc2[0]);
                    acc2[1]  = ffma2(wa.x, x1, acc2[1]);
                    acc2[2]  = ffma2(wa.y, x0, acc2[2]);
                    acc2[3]  = ffma2(wa.y, x1, acc2[3]);
                    acc2[4]  = ffma2(wb.x, x0, acc2[4]);
                    acc2[5]  = ffma2(wb.x, x1, acc2[5]);
                    acc2[6]  = ffma2(wb.y, x0, acc2[6]);
                    acc2[7]  = ffma2(wb.y, x1, acc2[7]);
                    acc2[8]  = ffma2(wcp.x, x0, acc2[8]);
                    acc2[9]  = ffma2(wcp.x, x1, acc2[9]);
                    acc2[10] = ffma2(wcp.y, x0, acc2[10]);
                    acc2[11] = ffma2(wcp.y, x1, acc2[11]);
                    acc2[12] = ffma2(wd.x, x0, acc2[12]);
                    acc2[13] = ffma2(wd.x, x1, acc2[13]);
                }
            }
        }
    }

    // store q tile: sq[ob*400 + h*50 + w]
    {
        const int h = hw0 / 40, w = hw0 - h * 40;   // hw0 even -> same h
        float* qb = sq + h * 50 + w;
#pragma unroll
        for (int p = 0; p < 7; p++) {
            float a0, a1, b0v, b1v;
            unpack2(acc2[2 * p],     a0, a1);   // (ob0+2p, ob0+2p+1) @ hw0
            unpack2(acc2[2 * p + 1], b0v, b1v); // same obs @ hw0+1
            float* r0 = qb + (ob0 + 2 * p) * 400;
            float* r1 = qb + (ob0 + 2 * p + 1) * 400;
            r0[0] = a0; r0[1] = b0v;
            r1[0] = a1; r1[1] = b1v;
        }
    }
    __syncthreads();   // sw dead; sacc (aliased) live

    // ---- Phase B: warp = (gpair, o); lane = (hc, chunk) ----------------------
    const int warpId = tid >> 5, lane = tid & 31;
    const int hcx   = lane >> 2;
    const int chunk = lane & 3;
    const int hc    = (hcx < 6) ? hcx : 5;     // idle lanes -> broadcast dup
    const int wc0   = chunk * 10;

#pragma unroll 1
    for (int wt = warpId; wt < 48; wt += 20) {
        const int gp = wt >> 3;                // 0..5
        const int o  = wt & 7;

        u64 accv[10];
#pragma unroll
        for (int i = 0; i < 10; i++) accv[i] = 0ull;

        const u64* bpb = (const u64*)(sbp) + gp * 63;
#pragma unroll 1
        for (int b = 0; b < 7; b++) {
            u64 bp[9];
#pragma unroll
            for (int t = 0; t < 9; t++) bp[t] = bpb[b * 9 + t];   // broadcast

            const float* qbase = sq + (o * 7 + b) * 400 + wc0;
#pragma unroll
            for (int u = 0; u < 3; u++) {
                const float* qr = qbase + (hc + u) * 50;
                u64 qp[12];
#pragma unroll
                for (int k = 0; k < 6; k++) {
                    const float2 qv = *(const float2*)(qr + 2 * k);
                    qp[2 * k]     = pack2(qv.x, qv.x);
                    qp[2 * k + 1] = pack2(qv.y, qv.y);
                }
                const u64 c0 = bp[u * 3 + 0], c1 = bp[u * 3 + 1], c2 = bp[u * 3 + 2];
#pragma unroll
                for (int i = 0; i < 10; i++)
                    accv[i] = ffma2(c0, qp[i],
                              ffma2(c1, qp[i + 1],
                              ffma2(c2, qp[i + 2], accv[i])));
            }
        }
        if (hcx < 6) {
            const int width = (chunk < 3) ? 10 : 8;
            float* a0p = sacc + (gp * 16 + o) * 234 + hc * 39 + wc0;
            float* a1p = a0p + 8 * 234;
#pragma unroll
            for (int i = 0; i < 10; i++) {
                if (i < width) {
                    float v0, v1;
                    unpack2(accv[i], v0, v1);
                    a0p[i] = v0;
                    a1p[i] = v1;
                }
            }
        }
    }
    __syncthreads();

    // ---- Phase C: analytic T/I/J gather, add bias, write out ----------------
    {
        const int hw   = tid % 320;
        const int half = tid / 320;
        const int h = hw / 40, w = hw - h * 40;
        const bool bord = (h == 0) | (h == 7) | (w == 0) | (w == 39);
        const int ii = min(max(h, 1), 6) - 1;
        const int jj = min(max(w, 1), 38) - 1;
        const int pix = ii * 39 + jj;
        const size_t obase = (size_t)bx * 320 + hw;
#pragma unroll 1
        for (int go = half; go < 96; go += 2) {
            const int g = go >> 3, o = go & 7;
            int gg = g;
            if (bord) { gg = g + 1; if (gg == 12) gg = 0; }
            const int idx = gg * 8 + o;
            const float v = sacc[idx * 234 + pix] + sbiasv[idx];
            out[(size_t)go * 552960 + obase] = v;
        }
    }
}

// ---------------------------------------------------------------------------
extern "C" void kernel_launch(void* const* d_in, const int* in_sizes, int n_in,
                              void* d_out, int out_size) {
    const float* x     = (const float*)d_in[0];
    const float* wgt   = (const float*)d_in[1];
    const float* bias  = (const float*)d_in[2];
    const float* basis = (const float*)d_in[3];
    const int*   bbg   = (const int*)d_in[7];
    float* out = (float*)d_out;

    cudaFuncSetAttribute(k_fused, cudaFuncAttributeMaxDynamicSharedMemorySize,
                         SMEM_BYTES);

    k_fused<<<1728, 640, SMEM_BYTES>>>(x, wgt, bias, basis, bbg, out);
}